// round 5
// baseline (speedup 1.0000x reference)
#include <cuda_runtime.h>
#include <cstdint>

#define BH   32
#define LSEQ 4096
#define DK   16
#define DV   64
#define CS   256
#define NC   16

#define ST_STRIDE 17792
#define OFF_KVQ 0
#define OFF_KVL 16384
#define OFF_KK  17408
#define OFF_KS  17664
#define OFF_VS  17680
#define ST_TOTAL 17744

__device__ float g_state[(size_t)BH * NC * ST_STRIDE];

__device__ __forceinline__ unsigned f2t(float x) {
    unsigned u;
    asm("cvt.rna.tf32.f32 %0, %1;" : "=r"(u) : "f"(x));
    return u;
}
__device__ __forceinline__ float f2tf(float x) { return __uint_as_float(f2t(x)); }
__device__ __forceinline__ unsigned fas(float x) { return __float_as_uint(x); }
__device__ __forceinline__ unsigned shflu(unsigned v, int src) {
    return __shfl_sync(0xffffffffu, v, src);
}

__device__ __forceinline__ void mma8(float* c, unsigned a0, unsigned a1,
                                     unsigned a2, unsigned a3,
                                     unsigned b0, unsigned b1) {
    asm volatile(
        "mma.sync.aligned.m16n8k8.row.col.f32.tf32.tf32.f32 "
        "{%0,%1,%2,%3},{%4,%5,%6,%7},{%8,%9},{%0,%1,%2,%3};"
        : "+f"(c[0]), "+f"(c[1]), "+f"(c[2]), "+f"(c[3])
        : "r"(a0), "r"(a1), "r"(a2), "r"(a3), "r"(b0), "r"(b1));
}

// ---------------------------------------------------------------------------
// Kernel 1: per-chunk state build. 1024 threads, 32 warps.
// warp: wm = warp>>2 (32 de-rows), wn = warp&3 (16 V-cols)
// ---------------------------------------------------------------------------
__global__ __launch_bounds__(1024, 1)
void k_build(const float* __restrict__ kin, const float* __restrict__ vin) {
    const int head = blockIdx.x, ch = blockIdx.y;
    extern __shared__ float sm[];
    float* sk = sm;                 // [256][17] tf32-rounded k
    float* sB = sk + CS * 17;       // [64][72]  tf32 V tile
    unsigned* sBu = (unsigned*)sB;

    const float* kg = kin + ((size_t)head * LSEQ + (size_t)ch * CS) * DK;
    const float* vg = vin + ((size_t)head * LSEQ + (size_t)ch * CS) * DV;
    float* st = g_state + (size_t)(head * NC + ch) * ST_STRIDE;

    const int tid = threadIdx.x, warp = tid >> 5, lane = tid & 31;
    const int wm = warp >> 2, wn = warp & 3, g = lane >> 2, tg = lane & 3;

    for (int i = tid; i < CS * DK; i += 1024)
        sk[(i >> 4) * 17 + (i & 15)] = f2tf(kg[i]);
    __syncthreads();

    float c[2][2][4];
    #pragma unroll
    for (int mt = 0; mt < 2; mt++)
        #pragma unroll
        for (int nt = 0; nt < 2; nt++)
            #pragma unroll
            for (int u = 0; u < 4; u++) c[mt][nt][u] = 0.f;

    const int kd_d = tid >> 6, kd_f = tid & 63;   // one (d,f) per thread
    float kvl = 0.f, vsm = 0.f;

    for (int t = 0; t < 4; t++) {
        {
            int cc = tid >> 4, f4 = (tid & 15) * 4;
            float4 v = *(const float4*)&vg[(t * 64 + cc) * 64 + f4];
            *(uint4*)&sBu[cc * 72 + f4] =
                make_uint4(f2t(v.x), f2t(v.y), f2t(v.z), f2t(v.w));
        }
        __syncthreads();
        #pragma unroll
        for (int ks = 0; ks < 8; ks++) {
            int c0 = t * 64 + 8 * ks + tg;
            const float* k0 = sk + c0 * 17;
            const float* k1 = k0 + 4 * 17;
            float e00 = k0[g], e01 = k0[g + 8];
            float e10 = k1[g], e11 = k1[g + 8];
            unsigned a[2][4];
            #pragma unroll
            for (int mt = 0; mt < 2; mt++) {
                int d = 2 * wm + mt;
                float kd0 = k0[d], kd1 = k1[d];
                a[mt][0] = fas(kd0 * e00);
                a[mt][1] = fas(kd0 * e01);
                a[mt][2] = fas(kd1 * e10);
                a[mt][3] = fas(kd1 * e11);
            }
            unsigned b[2][2];
            #pragma unroll
            for (int nt = 0; nt < 2; nt++) {
                int fc = 16 * wn + 8 * nt + g;
                b[nt][0] = sBu[(8 * ks + tg) * 72 + fc];
                b[nt][1] = sBu[(8 * ks + tg + 4) * 72 + fc];
            }
            #pragma unroll
            for (int mt = 0; mt < 2; mt++)
                #pragma unroll
                for (int nt = 0; nt < 2; nt++)
                    mma8(c[mt][nt], a[mt][0], a[mt][1], a[mt][2], a[mt][3],
                         b[nt][0], b[nt][1]);
        }
        // kvl / vsum partials (tf32 tile values are valid floats)
        #pragma unroll 4
        for (int cc = 0; cc < 64; cc++)
            kvl = fmaf(sk[(t * 64 + cc) * 17 + kd_d], sB[cc * 72 + kd_f], kvl);
        if (tid < 64) {
            #pragma unroll 4
            for (int cc = 0; cc < 64; cc++) vsm += sB[cc * 72 + tid];
        }
        __syncthreads();
    }

    #pragma unroll
    for (int mt = 0; mt < 2; mt++)
        #pragma unroll
        for (int nt = 0; nt < 2; nt++) {
            int r0 = 32 * wm + 16 * mt + g, f = 16 * wn + 8 * nt + 2 * tg;
            *(float2*)&st[OFF_KVQ + r0 * 64 + f] =
                make_float2(c[mt][nt][0], c[mt][nt][1]);
            *(float2*)&st[OFF_KVQ + (r0 + 8) * 64 + f] =
                make_float2(c[mt][nt][2], c[mt][nt][3]);
        }
    st[OFF_KVL + kd_d * 64 + kd_f] = kvl;

    {   // kksum: 4 threads per (d,e) pair
        int pair = tid >> 2, d = pair >> 4, e = pair & 15;
        int cc0 = (tid & 3) * 64;
        float s = 0.f;
        #pragma unroll 4
        for (int cc = cc0; cc < cc0 + 64; cc++)
            s = fmaf(sk[cc * 17 + d], sk[cc * 17 + e], s);
        s += __shfl_xor_sync(0xffffffffu, s, 1);
        s += __shfl_xor_sync(0xffffffffu, s, 2);
        if (!(tid & 3)) st[OFF_KK + pair] = s;
    }
    if (tid < DK) {
        float s = 0.f;
        #pragma unroll 4
        for (int cc = 0; cc < CS; cc++) s += sk[cc * 17 + tid];
        st[OFF_KS + tid] = s;
    }
    if (tid < DV) st[OFF_VS + tid] = vsm;
}

// ---------------------------------------------------------------------------
// Kernel 2: exclusive prefix scan over chunk axis.
// ---------------------------------------------------------------------------
__global__ void k_scan() {
    const int head = blockIdx.x;
    float* base = g_state + (size_t)head * NC * ST_STRIDE;
    for (int i = blockIdx.y * blockDim.x + threadIdx.x; i < ST_TOTAL;
         i += gridDim.y * blockDim.x) {
        float run = 0.f;
        #pragma unroll
        for (int c = 0; c < NC; c++) {
            float t = base[(size_t)c * ST_STRIDE + i];
            base[(size_t)c * ST_STRIDE + i] = run;
            run += t;
        }
    }
}

// ---------------------------------------------------------------------------
// Kernel 3: per-(head,chunk) output. 1024 threads, 32 warps, no sA staging.
// ---------------------------------------------------------------------------
__global__ __launch_bounds__(1024, 1)
void k_main(const float* __restrict__ qin, const float* __restrict__ kin,
            const float* __restrict__ vin, float* __restrict__ out) {
    const int head = blockIdx.x, ch = blockIdx.y;
    extern __shared__ float sm[];
    float* sq  = sm;                 // [256][17] tf32 (scaled q)
    float* sk  = sq + CS * 17;       // [256][17] tf32 k
    float* sB  = sk + CS * 17;       // [64][72]  staged B tile
    float* skk = sB + 64 * 72;       // [256]
    float* sks = skk + 256;          // [16]
    float* szs = sks + 16;           // [256]
    unsigned* sBu = (unsigned*)sB;

    const float* qg = qin + ((size_t)head * LSEQ + (size_t)ch * CS) * DK;
    const float* kg = kin + ((size_t)head * LSEQ + (size_t)ch * CS) * DK;
    const float* vg = vin + ((size_t)head * LSEQ + (size_t)ch * CS) * DV;
    const float* st = g_state + (size_t)(head * NC + ch) * ST_STRIDE;

    const int tid = threadIdx.x, warp = tid >> 5, lane = tid & 31;
    const int wm = warp >> 2, wn = warp & 3, g = lane >> 2, tg = lane & 3;
    const int rb = 32 * wm;

    for (int i = tid; i < CS * DK; i += 1024) {
        int r = i >> 4, cc = i & 15;
        sq[r * 17 + cc] = f2tf(qg[i] * 0.25f);
        sk[r * 17 + cc] = f2tf(kg[i]);
    }
    if (tid < 256) skk[tid] = st[OFF_KK + tid];
    if (tid < DK) sks[tid] = st[OFF_KS + tid];
    __syncthreads();

    // ---- closed-form z: count + linear + quadratic inter terms ----
    if (tid < 512) {
        int row = tid >> 1, dh = (tid & 1) * 8;
        float qr[16];
        #pragma unroll
        for (int d2 = 0; d2 < 16; d2++) qr[d2] = sq[row * 17 + d2];
        float zq = 0.f;
        #pragma unroll
        for (int d2 = dh; d2 < dh + 8; d2++) {
            float inner = 0.f;
            #pragma unroll
            for (int e2 = 0; e2 < 16; e2++)
                inner = fmaf(qr[e2], skk[d2 * 16 + e2], inner);
            zq = fmaf(qr[d2], inner, zq);
        }
        zq += __shfl_xor_sync(0xffffffffu, zq, 1);
        if (!(tid & 1)) {
            float zl = 0.f;
            #pragma unroll
            for (int d2 = 0; d2 < 16; d2++) zl = fmaf(qr[d2], sks[d2], zl);
            szs[row] = (float)(ch * CS) + 0.5f * zq + zl;
        }
    }
    __syncthreads();

    // preload Q fragments (own rows): used for S-mma and linear phase
    unsigned qf[2][2][4];
    #pragma unroll
    for (int mt = 0; mt < 2; mt++)
        #pragma unroll
        for (int ks = 0; ks < 2; ks++) {
            int r0 = rb + 16 * mt + g;
            qf[mt][ks][0] = fas(sq[r0 * 17 + 8 * ks + tg]);
            qf[mt][ks][1] = fas(sq[(r0 + 8) * 17 + 8 * ks + tg]);
            qf[mt][ks][2] = fas(sq[r0 * 17 + 8 * ks + tg + 4]);
            qf[mt][ks][3] = fas(sq[(r0 + 8) * 17 + 8 * ks + tg + 4]);
        }

    float c[2][2][4];
    #pragma unroll
    for (int mt = 0; mt < 2; mt++)
        #pragma unroll
        for (int nt = 0; nt < 2; nt++)
            #pragma unroll
            for (int u = 0; u < 4; u++) c[mt][nt][u] = 0.f;

    float zp[2][2];
    zp[0][0] = zp[0][1] = zp[1][0] = zp[1][1] = 0.f;
    const int srcA = (lane & ~3) + (tg >> 1), srcB = srcA + 2;
    const bool od = tg & 1;

    // ---- intra-chunk: S -> phi -> shuffle-permute -> AV mma, no smem A ----
    for (int jb = 0; jb < 4; jb++) {
        {
            int cc = tid >> 4, f4 = (tid & 15) * 4;
            float4 v = *(const float4*)&vg[(jb * 64 + cc) * 64 + f4];
            *(uint4*)&sBu[cc * 72 + f4] =
                make_uint4(f2t(v.x), f2t(v.y), f2t(v.z), f2t(v.w));
        }
        __syncthreads();
        if (wm >= 2 * jb) {
            #pragma unroll
            for (int j = 0; j < 8; j++) {
                int jc = jb * 64 + 8 * j + g;
                unsigned b00 = fas(sk[jc * 17 + tg]);
                unsigned b01 = fas(sk[jc * 17 + tg + 4]);
                unsigned b10 = fas(sk[jc * 17 + 8 + tg]);
                unsigned b11 = fas(sk[jc * 17 + 8 + tg + 4]);
                unsigned af[2][4];
                #pragma unroll
                for (int mt = 0; mt < 2; mt++) {
                    float sf[4] = {0.f, 0.f, 0.f, 0.f};
                    mma8(sf, qf[mt][0][0], qf[mt][0][1], qf[mt][0][2],
                         qf[mt][0][3], b00, b01);
                    mma8(sf, qf[mt][1][0], qf[mt][1][1], qf[mt][1][2],
                         qf[mt][1][3], b10, b11);
                    int r0 = rb + 16 * mt + g;
                    int jg = jb * 64 + 8 * j + 2 * tg;
                    float v0 = (r0 >= jg)     ? fmaf(0.5f * sf[0], sf[0], sf[0] + 1.f) : 0.f;
                    float v1 = (r0 >= jg + 1) ? fmaf(0.5f * sf[1], sf[1], sf[1] + 1.f) : 0.f;
                    float v2 = (r0 + 8 >= jg)     ? fmaf(0.5f * sf[2], sf[2], sf[2] + 1.f) : 0.f;
                    float v3 = (r0 + 8 >= jg + 1) ? fmaf(0.5f * sf[3], sf[3], sf[3] + 1.f) : 0.f;
                    zp[mt][0] += v0 + v1;
                    zp[mt][1] += v2 + v3;
                    unsigned u0 = f2t(v0), u1 = f2t(v1);
                    unsigned u2 = f2t(v2), u3 = f2t(v3);
                    // C-layout (g,2tg | g,2tg+1) -> A-layout (g,tg | g,tg+4)
                    unsigned e0 = shflu(u0, srcA), o0 = shflu(u1, srcA);
                    unsigned e1 = shflu(u2, srcA), o1 = shflu(u3, srcA);
                    unsigned e2 = shflu(u0, srcB), o2 = shflu(u1, srcB);
                    unsigned e3 = shflu(u2, srcB), o3 = shflu(u3, srcB);
                    af[mt][0] = od ? o0 : e0;
                    af[mt][1] = od ? o1 : e1;
                    af[mt][2] = od ? o2 : e2;
                    af[mt][3] = od ? o3 : e3;
                }
                unsigned bv[2][2];
                #pragma unroll
                for (int nt = 0; nt < 2; nt++) {
                    int fc = 16 * wn + 8 * nt + g;
                    bv[nt][0] = sBu[(8 * j + tg) * 72 + fc];
                    bv[nt][1] = sBu[(8 * j + tg + 4) * 72 + fc];
                }
                #pragma unroll
                for (int mt = 0; mt < 2; mt++)
                    #pragma unroll
                    for (int nt = 0; nt < 2; nt++)
                        mma8(c[mt][nt], af[mt][0], af[mt][1], af[mt][2],
                             af[mt][3], bv[nt][0], bv[nt][1]);
            }
        }
        __syncthreads();
    }

    // intra z contribution (one warp per row-block touches szs)
    if (wn == 0) {
        #pragma unroll
        for (int mt = 0; mt < 2; mt++)
            #pragma unroll
            for (int h = 0; h < 2; h++) {
                float v = zp[mt][h];
                v += __shfl_xor_sync(0xffffffffu, v, 1);
                v += __shfl_xor_sync(0xffffffffu, v, 2);
                if (tg == 0) szs[rb + 16 * mt + g + 8 * h] += v;
            }
    }

    // ---- quadratic inter: register A = 0.5*q_d*q_e; B = KVq_prev tile ----
    for (int qb = 0; qb < 4; qb++) {
        {
            int cc = tid >> 4, f4 = (tid & 15) * 4;
            float4 v = *(const float4*)&st[OFF_KVQ + qb * 4096 + cc * 64 + f4];
            *(uint4*)&sBu[cc * 72 + f4] =
                make_uint4(f2t(v.x), f2t(v.y), f2t(v.z), f2t(v.w));
        }
        __syncthreads();
        #pragma unroll
        for (int ks = 0; ks < 8; ks++) {
            int c0 = qb * 64 + 8 * ks + tg, c1 = c0 + 4;
            int d0 = c0 >> 4, e0 = c0 & 15;
            int d1 = c1 >> 4, e1 = c1 & 15;
            unsigned a[2][4];
            #pragma unroll
            for (int mt = 0; mt < 2; mt++) {
                int r = rb + 16 * mt + g;
                const float* q0 = sq + r * 17;
                const float* q1 = q0 + 8 * 17;
                a[mt][0] = fas(0.5f * q0[d0] * q0[e0]);
                a[mt][1] = fas(0.5f * q1[d0] * q1[e0]);
                a[mt][2] = fas(0.5f * q0[d1] * q0[e1]);
                a[mt][3] = fas(0.5f * q1[d1] * q1[e1]);
            }
            unsigned b[2][2];
            #pragma unroll
            for (int nt = 0; nt < 2; nt++) {
                int fc = 16 * wn + 8 * nt + g;
                b[nt][0] = sBu[(8 * ks + tg) * 72 + fc];
                b[nt][1] = sBu[(8 * ks + tg + 4) * 72 + fc];
            }
            #pragma unroll
            for (int mt = 0; mt < 2; mt++)
                #pragma unroll
                for (int nt = 0; nt < 2; nt++)
                    mma8(c[mt][nt], a[mt][0], a[mt][1], a[mt][2], a[mt][3],
                         b[nt][0], b[nt][1]);
        }
        __syncthreads();
    }

    // ---- linear inter: A = Q (qf), B = KVl_prev [16][64] ----
    if (tid < 256) {
        int cc = tid >> 4, f4 = (tid & 15) * 4;
        float4 v = *(const float4*)&st[OFF_KVL + cc * 64 + f4];
        *(uint4*)&sBu[cc * 72 + f4] =
            make_uint4(f2t(v.x), f2t(v.y), f2t(v.z), f2t(v.w));
    }
    __syncthreads();
    #pragma unroll
    for (int ks = 0; ks < 2; ks++) {
        unsigned b[2][2];
        #pragma unroll
        for (int nt = 0; nt < 2; nt++) {
            int fc = 16 * wn + 8 * nt + g;
            b[nt][0] = sBu[(8 * ks + tg) * 72 + fc];
            b[nt][1] = sBu[(8 * ks + tg + 4) * 72 + fc];
        }
        #pragma unroll
        for (int mt = 0; mt < 2; mt++)
            #pragma unroll
            for (int nt = 0; nt < 2; nt++)
                mma8(c[mt][nt], qf[mt][ks][0], qf[mt][ks][1],
                     qf[mt][ks][2], qf[mt][ks][3], b[nt][0], b[nt][1]);
    }
    __syncthreads();

    // ---- epilogue: add vsum_prev, divide by z, store ----
    float* og = out + ((size_t)head * LSEQ + (size_t)ch * CS) * DV;
    #pragma unroll
    for (int mt = 0; mt < 2; mt++) {
        int r0 = rb + 16 * mt + g;
        float z0 = 1.f / (szs[r0] + 1e-6f);
        float z1 = 1.f / (szs[r0 + 8] + 1e-6f);
        #pragma unroll
        for (int nt = 0; nt < 2; nt++) {
            int f = 16 * wn + 8 * nt + 2 * tg;
            float vs0 = st[OFF_VS + f], vs1 = st[OFF_VS + f + 1];
            *(float2*)&og[r0 * 64 + f] =
                make_float2((c[mt][nt][0] + vs0) * z0, (c[mt][nt][1] + vs1) * z0);
            *(float2*)&og[(r0 + 8) * 64 + f] =
                make_float2((c[mt][nt][2] + vs0) * z1, (c[mt][nt][3] + vs1) * z1);
        }
    }
}

// ---------------------------------------------------------------------------
extern "C" void kernel_launch(void* const* d_in, const int* in_sizes, int n_in,
                              void* d_out, int out_size) {
    const float* q = (const float*)d_in[0];
    const float* k = (const float*)d_in[1];
    const float* v = (const float*)d_in[2];
    float* out = (float*)d_out;

    const int smem1 = (CS * 17 + 64 * 72) * (int)sizeof(float);
    const int smem3 = (CS * 17 * 2 + 64 * 72 + 256 + 16 + 256) * (int)sizeof(float);

    cudaFuncSetAttribute(k_build, cudaFuncAttributeMaxDynamicSharedMemorySize, smem1);
    cudaFuncSetAttribute(k_main,  cudaFuncAttributeMaxDynamicSharedMemorySize, smem3);

    k_build<<<dim3(BH, NC), 1024, smem1>>>(k, v);
    k_scan<<<dim3(BH, 16), 256>>>();
    k_main<<<dim3(BH, NC), 1024, smem3>>>(q, k, v, out);
}

// round 6
// speedup vs baseline: 1.1766x; 1.1766x over previous
#include <cuda_runtime.h>
#include <cstdint>

#define BH   32
#define LSEQ 4096
#define DK   16
#define DV   64
#define CS   256
#define NC   16

// Symmetric-pair state: 136 pair rows (d<=e) + 16 linear rows + 1 ones row,
// padded to 160 rows x 72 cols (64 v-cols + 1 aux-sum col + 7 zero pads).
#define NP   160
#define NW   72
#define ST_STRIDE (NP * NW)   // 11520

__device__ float g_state[(size_t)BH * NC * ST_STRIDE];

__device__ __forceinline__ unsigned f2t(float x) {
    unsigned u;
    asm("cvt.rna.tf32.f32 %0, %1;" : "=r"(u) : "f"(x));
    return u;
}
__device__ __forceinline__ float f2tf(float x) { return __uint_as_float(f2t(x)); }
__device__ __forceinline__ unsigned fas(float x) { return __float_as_uint(x); }

__device__ __forceinline__ void mma8(float* c, unsigned a0, unsigned a1,
                                     unsigned a2, unsigned a3,
                                     unsigned b0, unsigned b1) {
    asm volatile(
        "mma.sync.aligned.m16n8k8.row.col.f32.tf32.tf32.f32 "
        "{%0,%1,%2,%3},{%4,%5,%6,%7},{%8,%9},{%0,%1,%2,%3};"
        : "+f"(c[0]), "+f"(c[1]), "+f"(c[2]), "+f"(c[3])
        : "r"(a0), "r"(a1), "r"(a2), "r"(a3), "r"(b0), "r"(b1));
}

// p -> (d, e, w).  d,e in [0,16]; index 16 hits the pad column (=1.0f).
__device__ __forceinline__ void lut_build(int* spd, int* spe, float* sw, int tid) {
    if (tid < NP) {
        int p = tid, d = 0, e;
        float w;
        if (p < 136) {
            int base = 0;
            while (base + (16 - d) <= p) { base += 16 - d; d++; }
            e = d + (p - base);
            w = (d == e) ? 0.5f : 1.0f;
        } else if (p < 152) { d = p - 136; e = 16; w = 1.f; }
        else if (p == 152) { d = 16; e = 16; w = 1.f; }
        else               { d = 16; e = 16; w = 0.f; }
        spd[p] = d; spe[p] = e; sw[p] = w;
    }
}

// ---------------------------------------------------------------------------
// Kernel 1: state build = single GEMM  st[160x72] = A[160x256] @ B[256x72]
// A[p][c] = k_{d(p)}[c] * k_{e(p)}[c]  (register-built, pad-col trick)
// B[c][0..63] = v,  B[c][64] = 1,  B[c][65..71] = 0
// 480 threads = 15 warps: wm = warp/3 (32 rows), wn = warp%3 (24 cols)
// ---------------------------------------------------------------------------
__global__ __launch_bounds__(480, 1)
void k_build(const float* __restrict__ kin, const float* __restrict__ vin) {
    const int head = blockIdx.x, ch = blockIdx.y;
    extern __shared__ float sm[];
    float* sk = sm;                     // [256][17], col 16 = 1.0 pad
    float* sB = sk + CS * 17;           // [64][72]
    int*   spd = (int*)(sB + 64 * NW);  // [160]
    int*   spe = spd + NP;              // [160]
    float* sw  = (float*)(spe + NP);    // [160] (unused here, keeps lut_build shared)
    unsigned* sBu = (unsigned*)sB;

    const float* kg = kin + ((size_t)head * LSEQ + (size_t)ch * CS) * DK;
    const float* vg = vin + ((size_t)head * LSEQ + (size_t)ch * CS) * DV;
    float* st = g_state + (size_t)(head * NC + ch) * ST_STRIDE;

    const int tid = threadIdx.x, warp = tid >> 5, lane = tid & 31;
    const int wm = warp / 3, wn = warp % 3, g = lane >> 2, tg = lane & 3;
    const int rb = 32 * wm, cb = 24 * wn;

    for (int i = tid; i < CS * DK; i += 480)
        sk[(i >> 4) * 17 + (i & 15)] = f2tf(kg[i]);
    for (int i = tid; i < CS; i += 480) sk[i * 17 + 16] = 1.0f;
    lut_build(spd, spe, sw, tid);
    __syncthreads();

    // per-thread row lookups (fixed for whole kernel)
    int rd[2][2], re[2][2];
    #pragma unroll
    for (int mt = 0; mt < 2; mt++) {
        int r0 = rb + 16 * mt + g;
        rd[mt][0] = spd[r0];     re[mt][0] = spe[r0];
        rd[mt][1] = spd[r0 + 8]; re[mt][1] = spe[r0 + 8];
    }

    float c[2][3][4];
    #pragma unroll
    for (int mt = 0; mt < 2; mt++)
        #pragma unroll
        for (int nt = 0; nt < 3; nt++)
            #pragma unroll
            for (int u = 0; u < 4; u++) c[mt][nt][u] = 0.f;

    for (int t = 0; t < 4; t++) {
        for (int i = tid; i < 64 * 18; i += 480) {
            int cc = i / 18, f4 = (i - cc * 18) * 4;
            uint4 w;
            if (f4 < 64) {
                float4 vv = *(const float4*)&vg[(t * 64 + cc) * 64 + f4];
                w = make_uint4(f2t(vv.x), f2t(vv.y), f2t(vv.z), f2t(vv.w));
            } else {
                w = make_uint4(f4 == 64 ? 0x3f800000u : 0u, 0u, 0u, 0u);
            }
            *(uint4*)&sBu[cc * NW + f4] = w;
        }
        __syncthreads();
        #pragma unroll
        for (int ks = 0; ks < 8; ks++) {
            const float* p0 = sk + (t * 64 + 8 * ks + tg) * 17;
            const float* p1 = p0 + 4 * 17;
            unsigned a[2][4];
            #pragma unroll
            for (int mt = 0; mt < 2; mt++) {
                a[mt][0] = fas(p0[rd[mt][0]] * p0[re[mt][0]]);
                a[mt][1] = fas(p0[rd[mt][1]] * p0[re[mt][1]]);
                a[mt][2] = fas(p1[rd[mt][0]] * p1[re[mt][0]]);
                a[mt][3] = fas(p1[rd[mt][1]] * p1[re[mt][1]]);
            }
            unsigned b[3][2];
            #pragma unroll
            for (int nt = 0; nt < 3; nt++) {
                int fc = cb + 8 * nt + g;
                b[nt][0] = sBu[(8 * ks + tg) * NW + fc];
                b[nt][1] = sBu[(8 * ks + tg + 4) * NW + fc];
            }
            #pragma unroll
            for (int mt = 0; mt < 2; mt++)
                #pragma unroll
                for (int nt = 0; nt < 3; nt++)
                    mma8(c[mt][nt], a[mt][0], a[mt][1], a[mt][2], a[mt][3],
                         b[nt][0], b[nt][1]);
        }
        __syncthreads();
    }

    #pragma unroll
    for (int mt = 0; mt < 2; mt++)
        #pragma unroll
        for (int nt = 0; nt < 3; nt++) {
            int r0 = rb + 16 * mt + g, col = cb + 8 * nt + 2 * tg;
            *(float2*)&st[r0 * NW + col] =
                make_float2(c[mt][nt][0], c[mt][nt][1]);
            *(float2*)&st[(r0 + 8) * NW + col] =
                make_float2(c[mt][nt][2], c[mt][nt][3]);
        }
}

// ---------------------------------------------------------------------------
// Kernel 2: exclusive prefix scan over chunk axis.
// ---------------------------------------------------------------------------
__global__ void k_scan() {
    const int head = blockIdx.x;
    float* base = g_state + (size_t)head * NC * ST_STRIDE;
    for (int i = blockIdx.y * blockDim.x + threadIdx.x; i < ST_STRIDE;
         i += gridDim.y * blockDim.x) {
        float run = 0.f;
        #pragma unroll
        for (int c = 0; c < NC; c++) {
            float t = base[(size_t)c * ST_STRIDE + i];
            base[(size_t)c * ST_STRIDE + i] = run;
            run += t;
        }
    }
}

// ---------------------------------------------------------------------------
// K=64 gemm from staged A (stride 68) + staged B (stride 72), intra phase.
// ---------------------------------------------------------------------------
__device__ __forceinline__ void gemm64(const unsigned* __restrict__ sAu,
                                       const unsigned* __restrict__ sBu,
                                       int rb, int wn, int g, int tg,
                                       float c[2][5][4]) {
    #pragma unroll
    for (int ks = 0; ks < 8; ks++) {
        unsigned a[2][4];
        #pragma unroll
        for (int mt = 0; mt < 2; mt++) {
            int rr = rb + 16 * mt + g;
            a[mt][0] = sAu[rr * 68 + 8 * ks + tg];
            a[mt][1] = sAu[(rr + 8) * 68 + 8 * ks + tg];
            a[mt][2] = sAu[rr * 68 + 8 * ks + tg + 4];
            a[mt][3] = sAu[(rr + 8) * 68 + 8 * ks + tg + 4];
        }
        unsigned b[4][2];
        #pragma unroll
        for (int nt = 0; nt < 4; nt++) {
            int fc = 32 * wn + 8 * nt + g;
            b[nt][0] = sBu[(8 * ks + tg) * NW + fc];
            b[nt][1] = sBu[(8 * ks + tg + 4) * NW + fc];
        }
        #pragma unroll
        for (int mt = 0; mt < 2; mt++)
            #pragma unroll
            for (int nt = 0; nt < 4; nt++)
                mma8(c[mt][nt], a[mt][0], a[mt][1], a[mt][2], a[mt][3],
                     b[nt][0], b[nt][1]);
    }
}

// ---------------------------------------------------------------------------
// Kernel 3: output. 512 threads, 16 warps: wm=warp>>1 (32 rows), wn=warp&1.
// Intra: staged phi(S) @ V (round-4 proven).  Inter: ONE GEMM vs scanned
// state [160x72]: cols 0..63 = o-contrib (quad+linear+vsum), col 64 = z-inter.
// ---------------------------------------------------------------------------
__global__ __launch_bounds__(512, 1)
void k_main(const float* __restrict__ qin, const float* __restrict__ kin,
            const float* __restrict__ vin, float* __restrict__ out) {
    const int head = blockIdx.x, ch = blockIdx.y;
    extern __shared__ float sm[];
    float* sq  = sm;                    // [256][17], col16 = 1.0 pad
    float* sk  = sq + CS * 17;          // [256][17]
    float* sA  = sk + CS * 17;          // [256][68] staged phi(S)
    float* sB  = sA + 256 * 68;         // [64][72]
    float* szs = sB + 64 * NW;          // [256]
    int*   spd = (int*)(szs + 256);     // [160]
    int*   spe = spd + NP;
    float* sw  = (float*)(spe + NP);    // [160]
    unsigned* sAu = (unsigned*)sA;
    unsigned* sBu = (unsigned*)sB;

    const float* qg = qin + ((size_t)head * LSEQ + (size_t)ch * CS) * DK;
    const float* kg = kin + ((size_t)head * LSEQ + (size_t)ch * CS) * DK;
    const float* vg = vin + ((size_t)head * LSEQ + (size_t)ch * CS) * DV;
    const float* st = g_state + (size_t)(head * NC + ch) * ST_STRIDE;

    const int tid = threadIdx.x, warp = tid >> 5, lane = tid & 31;
    const int wm = warp >> 1, wn = warp & 1, g = lane >> 2, tg = lane & 3;
    const int rb = 32 * wm;

    for (int i = tid; i < CS * DK; i += 512) {
        int r = i >> 4, cc = i & 15;
        sq[r * 17 + cc] = f2tf(qg[i] * 0.25f);
        sk[r * 17 + cc] = f2tf(kg[i]);
    }
    if (tid < 256) { sq[tid * 17 + 16] = 1.0f; szs[tid] = 0.f; }
    lut_build(spd, spe, sw, tid);
    __syncthreads();

    // Q fragments for the S-mma (K=16)
    unsigned qf[2][2][4];
    #pragma unroll
    for (int mt = 0; mt < 2; mt++)
        #pragma unroll
        for (int ks = 0; ks < 2; ks++) {
            int r0 = rb + 16 * mt + g;
            qf[mt][ks][0] = fas(sq[r0 * 17 + 8 * ks + tg]);
            qf[mt][ks][1] = fas(sq[(r0 + 8) * 17 + 8 * ks + tg]);
            qf[mt][ks][2] = fas(sq[r0 * 17 + 8 * ks + tg + 4]);
            qf[mt][ks][3] = fas(sq[(r0 + 8) * 17 + 8 * ks + tg + 4]);
        }

    float c[2][5][4];
    #pragma unroll
    for (int mt = 0; mt < 2; mt++)
        #pragma unroll
        for (int nt = 0; nt < 5; nt++)
            #pragma unroll
            for (int u = 0; u < 4; u++) c[mt][nt][u] = 0.f;

    float zp[2][2];
    zp[0][0] = zp[0][1] = zp[1][0] = zp[1][1] = 0.f;

    // ---- intra-chunk: A = mask(1 + S + 0.5 S^2) staged; B = V tile ----
    for (int jb = 0; jb < 4; jb++) {
        for (int i = tid; i < 1024; i += 512) {
            int cc = i >> 4, f4 = (i & 15) * 4;
            float4 v = *(const float4*)&vg[(jb * 64 + cc) * 64 + f4];
            *(uint4*)&sBu[cc * NW + f4] =
                make_uint4(f2t(v.x), f2t(v.y), f2t(v.z), f2t(v.w));
        }
        if (wm >= 2 * jb) {
            #pragma unroll
            for (int nt = 0; nt < 4; nt++) {
                int ca0 = 32 * wn + 8 * nt;
                unsigned bb[2][2];
                #pragma unroll
                for (int ks = 0; ks < 2; ks++) {
                    int jc = jb * 64 + ca0 + g;
                    bb[ks][0] = fas(sk[jc * 17 + 8 * ks + tg]);
                    bb[ks][1] = fas(sk[jc * 17 + 8 * ks + tg + 4]);
                }
                float sf[2][4];
                #pragma unroll
                for (int mt = 0; mt < 2; mt++)
                    #pragma unroll
                    for (int u = 0; u < 4; u++) sf[mt][u] = 0.f;
                #pragma unroll
                for (int ks = 0; ks < 2; ks++)
                    #pragma unroll
                    for (int mt = 0; mt < 2; mt++)
                        mma8(sf[mt], qf[mt][ks][0], qf[mt][ks][1],
                             qf[mt][ks][2], qf[mt][ks][3],
                             bb[ks][0], bb[ks][1]);
                #pragma unroll
                for (int mt = 0; mt < 2; mt++) {
                    int r0 = rb + 16 * mt + g;
                    int jg = jb * 64 + ca0 + 2 * tg;
                    float s0 = sf[mt][0], s1 = sf[mt][1];
                    float s2 = sf[mt][2], s3 = sf[mt][3];
                    float v0 = (r0 >= jg)     ? fmaf(0.5f * s0, s0, s0 + 1.f) : 0.f;
                    float v1 = (r0 >= jg + 1) ? fmaf(0.5f * s1, s1, s1 + 1.f) : 0.f;
                    float v2 = (r0 + 8 >= jg)     ? fmaf(0.5f * s2, s2, s2 + 1.f) : 0.f;
                    float v3 = (r0 + 8 >= jg + 1) ? fmaf(0.5f * s3, s3, s3 + 1.f) : 0.f;
                    *(uint2*)&sAu[r0 * 68 + ca0 + 2 * tg] =
                        make_uint2(f2t(v0), f2t(v1));
                    *(uint2*)&sAu[(r0 + 8) * 68 + ca0 + 2 * tg] =
                        make_uint2(f2t(v2), f2t(v3));
                    zp[mt][0] += v0 + v1;
                    zp[mt][1] += v2 + v3;
                }
            }
        }
        __syncthreads();
        if (wm >= 2 * jb) gemm64(sAu, sBu, rb, wn, g, tg, c);
        __syncthreads();
    }

    // intra z row-sums -> szs (quad-reduce then one atomic per row per warp)
    #pragma unroll
    for (int mt = 0; mt < 2; mt++)
        #pragma unroll
        for (int h = 0; h < 2; h++) {
            float v = zp[mt][h];
            v += __shfl_xor_sync(0xffffffffu, v, 1);
            v += __shfl_xor_sync(0xffffffffu, v, 2);
            if (tg == 0) atomicAdd(&szs[rb + 16 * mt + g + 8 * h], v);
        }

    // ---- inter: C[256x72] += A[256x160] @ (w * state)[160x72] ----
    for (int kt = 0; kt < 3; kt++) {
        const int np = (kt < 3 - 1) ? 64 : 32;
        for (int i = tid; i < np * 18; i += 512) {
            int pp = i / 18, f4 = (i - pp * 18) * 4;
            int p = kt * 64 + pp;
            float w = sw[p];
            float4 vv = *(const float4*)&st[p * NW + f4];
            *(uint4*)&sBu[pp * NW + f4] =
                make_uint4(f2t(w * vv.x), f2t(w * vv.y),
                           f2t(w * vv.z), f2t(w * vv.w));
        }
        __syncthreads();
        const int nks = (kt < 2) ? 8 : 4;
        const int ntn = 4 + wn, colb = 32 * wn;
        for (int ks = 0; ks < nks; ks++) {
            int p0 = kt * 64 + 8 * ks + tg, p1 = p0 + 4;
            int d0 = spd[p0], e0 = spe[p0];
            int d1 = spd[p1], e1 = spe[p1];
            unsigned a[2][4];
            #pragma unroll
            for (int mt = 0; mt < 2; mt++) {
                const float* qr0 = sq + (rb + 16 * mt + g) * 17;
                const float* qr1 = qr0 + 8 * 17;
                a[mt][0] = fas(qr0[d0] * qr0[e0]);
                a[mt][1] = fas(qr1[d0] * qr1[e0]);
                a[mt][2] = fas(qr0[d1] * qr0[e1]);
                a[mt][3] = fas(qr1[d1] * qr1[e1]);
            }
            unsigned b[5][2];
            #pragma unroll
            for (int nt = 0; nt < 5; nt++) {
                if (nt < ntn) {
                    int fc = colb + 8 * nt + g;
                    b[nt][0] = sBu[(8 * ks + tg) * NW + fc];
                    b[nt][1] = sBu[(8 * ks + tg + 4) * NW + fc];
                }
            }
            #pragma unroll
            for (int mt = 0; mt < 2; mt++)
                #pragma unroll
                for (int nt = 0; nt < 5; nt++)
                    if (nt < ntn)
                        mma8(c[mt][nt], a[mt][0], a[mt][1], a[mt][2],
                             a[mt][3], b[nt][0], b[nt][1]);
        }
        __syncthreads();
    }

    // z-inter lives in col 64 = (wn==1, nt==4, 2tg+u==0)
    if (wn == 1 && tg == 0) {
        #pragma unroll
        for (int mt = 0; mt < 2; mt++) {
            int r0 = rb + 16 * mt + g;
            szs[r0]     += c[mt][4][0];
            szs[r0 + 8] += c[mt][4][2];
        }
    }
    __syncthreads();

    // ---- epilogue: divide by z, store cols 0..63 ----
    float* og = out + ((size_t)head * LSEQ + (size_t)ch * CS) * DV;
    #pragma unroll
    for (int mt = 0; mt < 2; mt++) {
        int r0 = rb + 16 * mt + g;
        float z0 = 1.f / (szs[r0] + 1e-6f);
        float z1 = 1.f / (szs[r0 + 8] + 1e-6f);
        #pragma unroll
        for (int nt = 0; nt < 4; nt++) {
            int f = 32 * wn + 8 * nt + 2 * tg;
            *(float2*)&og[r0 * 64 + f] =
                make_float2(c[mt][nt][0] * z0, c[mt][nt][1] * z0);
            *(float2*)&og[(r0 + 8) * 64 + f] =
                make_float2(c[mt][nt][2] * z1, c[mt][nt][3] * z1);
        }
    }
}

// ---------------------------------------------------------------------------
extern "C" void kernel_launch(void* const* d_in, const int* in_sizes, int n_in,
                              void* d_out, int out_size) {
    const float* q = (const float*)d_in[0];
    const float* k = (const float*)d_in[1];
    const float* v = (const float*)d_in[2];
    float* out = (float*)d_out;

    const int smem1 = (CS * 17 + 64 * NW + 3 * NP) * (int)sizeof(float);
    const int smem3 = (CS * 17 * 2 + 256 * 68 + 64 * NW + 256 + 3 * NP) *
                      (int)sizeof(float);

    cudaFuncSetAttribute(k_build, cudaFuncAttributeMaxDynamicSharedMemorySize, smem1);
    cudaFuncSetAttribute(k_main,  cudaFuncAttributeMaxDynamicSharedMemorySize, smem3);

    k_build<<<dim3(BH, NC), 480, smem1>>>(k, v);
    k_scan<<<dim3(BH, 16), 256>>>();
    k_main<<<dim3(BH, NC), 512, smem3>>>(q, k, v, out);
}

// round 7
// speedup vs baseline: 1.7098x; 1.4532x over previous
#include <cuda_runtime.h>
#include <cstdint>

#define BH   32
#define LSEQ 4096
#define DK   16
#define DV   64
#define CS   256
#define NC   16

// Symmetric-pair state: 136 pair rows (d<=e) + 16 linear rows + 1 ones row,
// padded to 160 rows x 72 cols (64 v-cols + 1 aux-sum col + 7 zero pads).
#define NP   160
#define NW   72
#define ST_STRIDE (NP * NW)   // 11520

__device__ float g_state[(size_t)BH * NC * ST_STRIDE];

__device__ __forceinline__ unsigned f2t(float x) {
    unsigned u;
    asm("cvt.rna.tf32.f32 %0, %1;" : "=r"(u) : "f"(x));
    return u;
}
__device__ __forceinline__ float f2tf(float x) { return __uint_as_float(f2t(x)); }
__device__ __forceinline__ unsigned fas(float x) { return __float_as_uint(x); }
__device__ __forceinline__ unsigned shflu(unsigned v, int src) {
    return __shfl_sync(0xffffffffu, v, src);
}

__device__ __forceinline__ void mma8(float* c, unsigned a0, unsigned a1,
                                     unsigned a2, unsigned a3,
                                     unsigned b0, unsigned b1) {
    asm volatile(
        "mma.sync.aligned.m16n8k8.row.col.f32.tf32.tf32.f32 "
        "{%0,%1,%2,%3},{%4,%5,%6,%7},{%8,%9},{%0,%1,%2,%3};"
        : "+f"(c[0]), "+f"(c[1]), "+f"(c[2]), "+f"(c[3])
        : "r"(a0), "r"(a1), "r"(a2), "r"(a3), "r"(b0), "r"(b1));
}

// p -> (d, e, w).  d,e in [0,16]; index 16 hits the pad column (=1.0f).
__device__ __forceinline__ void lut_build(int* spd, int* spe, float* sw, int tid) {
    if (tid < NP) {
        int p = tid, d = 0, e;
        float w;
        if (p < 136) {
            int base = 0;
            while (base + (16 - d) <= p) { base += 16 - d; d++; }
            e = d + (p - base);
            w = (d == e) ? 0.5f : 1.0f;
        } else if (p < 152) { d = p - 136; e = 16; w = 1.f; }
        else if (p == 152) { d = 16; e = 16; w = 1.f; }
        else               { d = 16; e = 16; w = 0.f; }
        spd[p] = d; spe[p] = e; sw[p] = w;
    }
}

// ---------------------------------------------------------------------------
// Kernel 1: state build = single GEMM  st[160x72] = A[160x256] @ B[256x72]
// Full B staged once; ONE barrier; unrolled 32-step mma stream.
// 480 threads = 15 warps: wm = warp/3 (32 rows), wn = warp%3 (24 cols)
// ---------------------------------------------------------------------------
__global__ __launch_bounds__(480, 1)
void k_build(const float* __restrict__ kin, const float* __restrict__ vin) {
    const int head = blockIdx.x, ch = blockIdx.y;
    extern __shared__ float sm[];
    float* sk = sm;                     // [256][17], col 16 = 1.0 pad
    float* sB = sk + CS * 17;           // [256][72] full V + aux
    int*   spd = (int*)(sB + CS * NW);  // [160]
    int*   spe = spd + NP;              // [160]
    float* sw  = (float*)(spe + NP);    // [160]
    unsigned* sBu = (unsigned*)sB;

    const float* kg = kin + ((size_t)head * LSEQ + (size_t)ch * CS) * DK;
    const float* vg = vin + ((size_t)head * LSEQ + (size_t)ch * CS) * DV;
    float* st = g_state + (size_t)(head * NC + ch) * ST_STRIDE;

    const int tid = threadIdx.x, warp = tid >> 5, lane = tid & 31;
    const int wm = warp / 3, wn = warp % 3, g = lane >> 2, tg = lane & 3;
    const int rb = 32 * wm, cb = 24 * wn;

    for (int i = tid; i < CS * DK; i += 480)
        sk[(i >> 4) * 17 + (i & 15)] = f2tf(kg[i]);
    for (int i = tid; i < CS; i += 480) sk[i * 17 + 16] = 1.0f;
    for (int i = tid; i < CS * 18; i += 480) {
        int cc = i / 18, f4 = (i - cc * 18) * 4;
        uint4 w;
        if (f4 < 64) {
            float4 vv = *(const float4*)&vg[cc * 64 + f4];
            w = make_uint4(f2t(vv.x), f2t(vv.y), f2t(vv.z), f2t(vv.w));
        } else {
            w = make_uint4(f4 == 64 ? 0x3f800000u : 0u, 0u, 0u, 0u);
        }
        *(uint4*)&sBu[cc * NW + f4] = w;
    }
    lut_build(spd, spe, sw, tid);
    __syncthreads();

    int rd[2][2], re[2][2];
    #pragma unroll
    for (int mt = 0; mt < 2; mt++) {
        int r0 = rb + 16 * mt + g;
        rd[mt][0] = spd[r0];     re[mt][0] = spe[r0];
        rd[mt][1] = spd[r0 + 8]; re[mt][1] = spe[r0 + 8];
    }

    float c[2][3][4];
    #pragma unroll
    for (int mt = 0; mt < 2; mt++)
        #pragma unroll
        for (int nt = 0; nt < 3; nt++)
            #pragma unroll
            for (int u = 0; u < 4; u++) c[mt][nt][u] = 0.f;

    #pragma unroll 8
    for (int ks = 0; ks < 32; ks++) {
        const float* p0 = sk + (8 * ks + tg) * 17;
        const float* p1 = p0 + 4 * 17;
        unsigned a[2][4];
        #pragma unroll
        for (int mt = 0; mt < 2; mt++) {
            a[mt][0] = fas(p0[rd[mt][0]] * p0[re[mt][0]]);
            a[mt][1] = fas(p0[rd[mt][1]] * p0[re[mt][1]]);
            a[mt][2] = fas(p1[rd[mt][0]] * p1[re[mt][0]]);
            a[mt][3] = fas(p1[rd[mt][1]] * p1[re[mt][1]]);
        }
        unsigned b[3][2];
        #pragma unroll
        for (int nt = 0; nt < 3; nt++) {
            int fc = cb + 8 * nt + g;
            b[nt][0] = sBu[(8 * ks + tg) * NW + fc];
            b[nt][1] = sBu[(8 * ks + tg + 4) * NW + fc];
        }
        #pragma unroll
        for (int mt = 0; mt < 2; mt++)
            #pragma unroll
            for (int nt = 0; nt < 3; nt++)
                mma8(c[mt][nt], a[mt][0], a[mt][1], a[mt][2], a[mt][3],
                     b[nt][0], b[nt][1]);
    }

    #pragma unroll
    for (int mt = 0; mt < 2; mt++)
        #pragma unroll
        for (int nt = 0; nt < 3; nt++) {
            int r0 = rb + 16 * mt + g, col = cb + 8 * nt + 2 * tg;
            *(float2*)&st[r0 * NW + col] =
                make_float2(c[mt][nt][0], c[mt][nt][1]);
            *(float2*)&st[(r0 + 8) * NW + col] =
                make_float2(c[mt][nt][2], c[mt][nt][3]);
        }
}

// ---------------------------------------------------------------------------
// Kernel 2: exclusive prefix scan over chunk axis.
// ---------------------------------------------------------------------------
__global__ void k_scan() {
    const int head = blockIdx.x;
    float* base = g_state + (size_t)head * NC * ST_STRIDE;
    for (int i = blockIdx.y * blockDim.x + threadIdx.x; i < ST_STRIDE;
         i += gridDim.y * blockDim.x) {
        float run = 0.f;
        #pragma unroll
        for (int c = 0; c < NC; c++) {
            float t = base[(size_t)c * ST_STRIDE + i];
            base[(size_t)c * ST_STRIDE + i] = run;
            run += t;
        }
    }
}

// ---------------------------------------------------------------------------
// Kernel 3: output. 512 threads: wm=warp>>1 (32 rows), wn=warp&1 (32 V-cols).
// Full V staged once; barrier-free shuffle intra; state restaged into same
// buffer; single unrolled inter GEMM. 4 barriers total.
// ---------------------------------------------------------------------------
__global__ __launch_bounds__(512, 1)
void k_main(const float* __restrict__ qin, const float* __restrict__ kin,
            const float* __restrict__ vin, float* __restrict__ out) {
    const int head = blockIdx.x, ch = blockIdx.y;
    extern __shared__ float sm[];
    float* sq  = sm;                    // [256][17], col16 = 1.0 pad
    float* sk  = sq + CS * 17;          // [256][17]
    float* sB  = sk + CS * 17;          // [256][72] V, later state[160][72]
    float* szs = sB + CS * NW;          // [256]
    int*   spd = (int*)(szs + 256);     // [160]
    int*   spe = spd + NP;
    float* sw  = (float*)(spe + NP);    // [160]
    unsigned* sBu = (unsigned*)sB;

    const float* qg = qin + ((size_t)head * LSEQ + (size_t)ch * CS) * DK;
    const float* kg = kin + ((size_t)head * LSEQ + (size_t)ch * CS) * DK;
    const float* vg = vin + ((size_t)head * LSEQ + (size_t)ch * CS) * DV;
    const float* st = g_state + (size_t)(head * NC + ch) * ST_STRIDE;

    const int tid = threadIdx.x, warp = tid >> 5, lane = tid & 31;
    const int wm = warp >> 1, wn = warp & 1, g = lane >> 2, tg = lane & 3;
    const int rb = 32 * wm;

    for (int i = tid; i < CS * DK; i += 512) {
        int r = i >> 4, cc = i & 15;
        sq[r * 17 + cc] = f2tf(qg[i] * 0.25f);
        sk[r * 17 + cc] = f2tf(kg[i]);
    }
    if (tid < 256) { sq[tid * 17 + 16] = 1.0f; szs[tid] = 0.f; }
    for (int i = tid; i < CS * 16; i += 512) {
        int cc = i >> 4, f4 = (i & 15) * 4;
        float4 v = *(const float4*)&vg[cc * 64 + f4];
        *(uint4*)&sBu[cc * NW + f4] =
            make_uint4(f2t(v.x), f2t(v.y), f2t(v.z), f2t(v.w));
    }
    lut_build(spd, spe, sw, tid);
    __syncthreads();

    // Q fragments (K=16 split as 2 x K=8)
    unsigned qf[2][2][4];
    #pragma unroll
    for (int mt = 0; mt < 2; mt++)
        #pragma unroll
        for (int ks = 0; ks < 2; ks++) {
            int r0 = rb + 16 * mt + g;
            qf[mt][ks][0] = fas(sq[r0 * 17 + 8 * ks + tg]);
            qf[mt][ks][1] = fas(sq[(r0 + 8) * 17 + 8 * ks + tg]);
            qf[mt][ks][2] = fas(sq[r0 * 17 + 8 * ks + tg + 4]);
            qf[mt][ks][3] = fas(sq[(r0 + 8) * 17 + 8 * ks + tg + 4]);
        }

    float c[2][5][4];
    #pragma unroll
    for (int mt = 0; mt < 2; mt++)
        #pragma unroll
        for (int nt = 0; nt < 5; nt++)
            #pragma unroll
            for (int u = 0; u < 4; u++) c[mt][nt][u] = 0.f;

    float zp[2][2];
    zp[0][0] = zp[0][1] = zp[1][0] = zp[1][1] = 0.f;
    const int srcA = (lane & ~3) + (tg >> 1), srcB = srcA + 2;
    const bool od = tg & 1;

    // ---- intra: barrier-free. S-mma -> phi -> shuffle -> AV-mma ----
    for (int jb = 0; jb < 4; jb++) {
        if (wm < 2 * jb) continue;
        #pragma unroll
        for (int j = 0; j < 8; j++) {
            int jc = jb * 64 + 8 * j + g;
            unsigned b00 = fas(sk[jc * 17 + tg]);
            unsigned b01 = fas(sk[jc * 17 + tg + 4]);
            unsigned b10 = fas(sk[jc * 17 + 8 + tg]);
            unsigned b11 = fas(sk[jc * 17 + 8 + tg + 4]);
            unsigned af[2][4];
            #pragma unroll
            for (int mt = 0; mt < 2; mt++) {
                float sf[4] = {0.f, 0.f, 0.f, 0.f};
                mma8(sf, qf[mt][0][0], qf[mt][0][1], qf[mt][0][2],
                     qf[mt][0][3], b00, b01);
                mma8(sf, qf[mt][1][0], qf[mt][1][1], qf[mt][1][2],
                     qf[mt][1][3], b10, b11);
                int r0 = rb + 16 * mt + g;
                int jg = jb * 64 + 8 * j + 2 * tg;
                float s0 = sf[0], s1 = sf[1], s2 = sf[2], s3 = sf[3];
                float v0 = (r0 >= jg)     ? fmaf(0.5f * s0, s0, s0 + 1.f) : 0.f;
                float v1 = (r0 >= jg + 1) ? fmaf(0.5f * s1, s1, s1 + 1.f) : 0.f;
                float v2 = (r0 + 8 >= jg)     ? fmaf(0.5f * s2, s2, s2 + 1.f) : 0.f;
                float v3 = (r0 + 8 >= jg + 1) ? fmaf(0.5f * s3, s3, s3 + 1.f) : 0.f;
                zp[mt][0] += v0 + v1;
                zp[mt][1] += v2 + v3;
                unsigned u0 = f2t(v0), u1 = f2t(v1);
                unsigned u2 = f2t(v2), u3 = f2t(v3);
                unsigned e0 = shflu(u0, srcA), o0 = shflu(u1, srcA);
                unsigned e1 = shflu(u2, srcA), o1 = shflu(u3, srcA);
                unsigned e2 = shflu(u0, srcB), o2 = shflu(u1, srcB);
                unsigned e3 = shflu(u2, srcB), o3 = shflu(u3, srcB);
                af[mt][0] = od ? o0 : e0;
                af[mt][1] = od ? o1 : e1;
                af[mt][2] = od ? o2 : e2;
                af[mt][3] = od ? o3 : e3;
            }
            #pragma unroll
            for (int nt = 0; nt < 4; nt++) {
                int fc = 32 * wn + 8 * nt + g;
                unsigned bv0 = sBu[(jb * 64 + 8 * j + tg) * NW + fc];
                unsigned bv1 = sBu[(jb * 64 + 8 * j + tg + 4) * NW + fc];
                #pragma unroll
                for (int mt = 0; mt < 2; mt++)
                    mma8(c[mt][nt], af[mt][0], af[mt][1], af[mt][2],
                         af[mt][3], bv0, bv1);
            }
        }
    }

    // intra z merge: wn==0 warps own their rows exclusively
    if (wn == 0) {
        #pragma unroll
        for (int mt = 0; mt < 2; mt++)
            #pragma unroll
            for (int h = 0; h < 2; h++) {
                float v = zp[mt][h];
                v += __shfl_xor_sync(0xffffffffu, v, 1);
                v += __shfl_xor_sync(0xffffffffu, v, 2);
                if (tg == 0) szs[rb + 16 * mt + g + 8 * h] += v;
            }
    }
    __syncthreads();   // V reads + szs intra writes complete

    // restage sB <- w * scanned state [160][72]
    for (int i = tid; i < NP * 18; i += 512) {
        int pp = i / 18, f4 = (i - pp * 18) * 4;
        float w = sw[pp];
        float4 vv = *(const float4*)&st[pp * NW + f4];
        *(uint4*)&sBu[pp * NW + f4] =
            make_uint4(f2t(w * vv.x), f2t(w * vv.y),
                       f2t(w * vv.z), f2t(w * vv.w));
    }
    __syncthreads();

    // ---- inter: C[256x72] += A[256x160] @ Bstate[160x72], unrolled ----
    const int ntn = 4 + wn, colb = 32 * wn;
    #pragma unroll 5
    for (int ks = 0; ks < 20; ks++) {
        int p0 = 8 * ks + tg, p1 = p0 + 4;
        int d0 = spd[p0], e0 = spe[p0];
        int d1 = spd[p1], e1 = spe[p1];
        unsigned a[2][4];
        #pragma unroll
        for (int mt = 0; mt < 2; mt++) {
            const float* qr0 = sq + (rb + 16 * mt + g) * 17;
            const float* qr1 = qr0 + 8 * 17;
            a[mt][0] = fas(qr0[d0] * qr0[e0]);
            a[mt][1] = fas(qr1[d0] * qr1[e0]);
            a[mt][2] = fas(qr0[d1] * qr0[e1]);
            a[mt][3] = fas(qr1[d1] * qr1[e1]);
        }
        unsigned b[5][2];
        #pragma unroll
        for (int nt = 0; nt < 5; nt++) {
            if (nt < ntn) {
                int fc = colb + 8 * nt + g;
                b[nt][0] = sBu[(8 * ks + tg) * NW + fc];
                b[nt][1] = sBu[(8 * ks + tg + 4) * NW + fc];
            }
        }
        #pragma unroll
        for (int mt = 0; mt < 2; mt++)
            #pragma unroll
            for (int nt = 0; nt < 5; nt++)
                if (nt < ntn)
                    mma8(c[mt][nt], a[mt][0], a[mt][1], a[mt][2],
                         a[mt][3], b[nt][0], b[nt][1]);
    }

    // z-inter lives in col 64 = (wn==1, nt==4, first col of pair)
    if (wn == 1 && tg == 0) {
        #pragma unroll
        for (int mt = 0; mt < 2; mt++) {
            int r0 = rb + 16 * mt + g;
            szs[r0]     += c[mt][4][0];
            szs[r0 + 8] += c[mt][4][2];
        }
    }
    __syncthreads();

    // ---- epilogue: divide by z, store ----
    float* og = out + ((size_t)head * LSEQ + (size_t)ch * CS) * DV;
    #pragma unroll
    for (int mt = 0; mt < 2; mt++) {
        int r0 = rb + 16 * mt + g;
        float z0 = 1.f / (szs[r0] + 1e-6f);
        float z1 = 1.f / (szs[r0 + 8] + 1e-6f);
        #pragma unroll
        for (int nt = 0; nt < 4; nt++) {
            int f = 32 * wn + 8 * nt + 2 * tg;
            *(float2*)&og[r0 * 64 + f] =
                make_float2(c[mt][nt][0] * z0, c[mt][nt][1] * z0);
            *(float2*)&og[(r0 + 8) * 64 + f] =
                make_float2(c[mt][nt][2] * z1, c[mt][nt][3] * z1);
        }
    }
}

// ---------------------------------------------------------------------------
extern "C" void kernel_launch(void* const* d_in, const int* in_sizes, int n_in,
                              void* d_out, int out_size) {
    const float* q = (const float*)d_in[0];
    const float* k = (const float*)d_in[1];
    const float* v = (const float*)d_in[2];
    float* out = (float*)d_out;

    const int smem1 = (CS * 17 + CS * NW + 3 * NP) * (int)sizeof(float);
    const int smem3 = (CS * 17 * 2 + CS * NW + 256 + 3 * NP) * (int)sizeof(float);

    cudaFuncSetAttribute(k_build, cudaFuncAttributeMaxDynamicSharedMemorySize, smem1);
    cudaFuncSetAttribute(k_main,  cudaFuncAttributeMaxDynamicSharedMemorySize, smem3);

    k_build<<<dim3(BH, NC), 480, smem1>>>(k, v);
    k_scan<<<dim3(BH, 16), 256>>>();
    k_main<<<dim3(BH, NC), 512, smem3>>>(q, k, v, out);
}

// round 8
// speedup vs baseline: 1.8999x; 1.1112x over previous
#include <cuda_runtime.h>
#include <cstdint>

#define BH   32
#define LSEQ 4096
#define DK   16
#define DV   64
#define CS   256
#define NC   16

// Symmetric-pair state: 136 pair rows (d<=e) + 16 linear rows + 1 ones row,
// padded to 160 rows x 72 cols (64 v-cols + 1 aux-sum col + 7 zero pads).
#define NP   160
#define NW   72
#define ST_STRIDE (NP * NW)   // 11520

__device__ float g_state[(size_t)BH * NC * ST_STRIDE];

__device__ __forceinline__ unsigned f2t(float x) {
    unsigned u;
    asm("cvt.rna.tf32.f32 %0, %1;" : "=r"(u) : "f"(x));
    return u;
}
__device__ __forceinline__ float f2tf(float x) { return __uint_as_float(f2t(x)); }
__device__ __forceinline__ unsigned fas(float x) { return __float_as_uint(x); }
__device__ __forceinline__ unsigned shflu(unsigned v, int src) {
    return __shfl_sync(0xffffffffu, v, src);
}

__device__ __forceinline__ void mma8(float* c, unsigned a0, unsigned a1,
                                     unsigned a2, unsigned a3,
                                     unsigned b0, unsigned b1) {
    asm volatile(
        "mma.sync.aligned.m16n8k8.row.col.f32.tf32.tf32.f32 "
        "{%0,%1,%2,%3},{%4,%5,%6,%7},{%8,%9},{%0,%1,%2,%3};"
        : "+f"(c[0]), "+f"(c[1]), "+f"(c[2]), "+f"(c[3])
        : "r"(a0), "r"(a1), "r"(a2), "r"(a3), "r"(b0), "r"(b1));
}

// p -> (d, e, w).  d,e in [0,16]; index 16 hits the pad column (=1.0f).
__device__ __forceinline__ void lut_build(int* spd, int* spe, float* sw, int tid) {
    if (tid < NP) {
        int p = tid, d = 0, e;
        float w;
        if (p < 136) {
            int base = 0;
            while (base + (16 - d) <= p) { base += 16 - d; d++; }
            e = d + (p - base);
            w = (d == e) ? 0.5f : 1.0f;
        } else if (p < 152) { d = p - 136; e = 16; w = 1.f; }
        else if (p == 152) { d = 16; e = 16; w = 1.f; }
        else               { d = 16; e = 16; w = 0.f; }
        spd[p] = d; spe[p] = e; sw[p] = w;
    }
}

// ---------------------------------------------------------------------------
// Kernel 1: state build = single GEMM  st[160x72] = A[160x256] @ B[256x72]
// Full B staged once; ONE barrier; unrolled 32-step mma stream.
// 480 threads = 15 warps, 2 CTAs/SM (regs capped).
// ---------------------------------------------------------------------------
__global__ __launch_bounds__(480, 2)
void k_build(const float* __restrict__ kin, const float* __restrict__ vin) {
    const int head = blockIdx.x, ch = blockIdx.y;
    extern __shared__ float sm[];
    float* sk = sm;                     // [256][17], col 16 = 1.0 pad
    float* sB = sk + CS * 17;           // [256][72] full V + aux
    int*   spd = (int*)(sB + CS * NW);  // [160]
    int*   spe = spd + NP;              // [160]
    float* sw  = (float*)(spe + NP);    // [160]
    unsigned* sBu = (unsigned*)sB;

    const float* kg = kin + ((size_t)head * LSEQ + (size_t)ch * CS) * DK;
    const float* vg = vin + ((size_t)head * LSEQ + (size_t)ch * CS) * DV;
    float* st = g_state + (size_t)(head * NC + ch) * ST_STRIDE;

    const int tid = threadIdx.x, warp = tid >> 5, lane = tid & 31;
    const int wm = warp / 3, wn = warp % 3, g = lane >> 2, tg = lane & 3;
    const int rb = 32 * wm, cb = 24 * wn;

    for (int i = tid; i < CS * DK; i += 480)
        sk[(i >> 4) * 17 + (i & 15)] = f2tf(kg[i]);
    for (int i = tid; i < CS; i += 480) sk[i * 17 + 16] = 1.0f;
    for (int i = tid; i < CS * 18; i += 480) {
        int cc = i / 18, f4 = (i - cc * 18) * 4;
        uint4 w;
        if (f4 < 64) {
            float4 vv = *(const float4*)&vg[cc * 64 + f4];
            w = make_uint4(f2t(vv.x), f2t(vv.y), f2t(vv.z), f2t(vv.w));
        } else {
            w = make_uint4(f4 == 64 ? 0x3f800000u : 0u, 0u, 0u, 0u);
        }
        *(uint4*)&sBu[cc * NW + f4] = w;
    }
    lut_build(spd, spe, sw, tid);
    __syncthreads();

    int rd[2][2], re[2][2];
    #pragma unroll
    for (int mt = 0; mt < 2; mt++) {
        int r0 = rb + 16 * mt + g;
        rd[mt][0] = spd[r0];     re[mt][0] = spe[r0];
        rd[mt][1] = spd[r0 + 8]; re[mt][1] = spe[r0 + 8];
    }

    float c[2][3][4];
    #pragma unroll
    for (int mt = 0; mt < 2; mt++)
        #pragma unroll
        for (int nt = 0; nt < 3; nt++)
            #pragma unroll
            for (int u = 0; u < 4; u++) c[mt][nt][u] = 0.f;

    #pragma unroll 4
    for (int ks = 0; ks < 32; ks++) {
        const float* p0 = sk + (8 * ks + tg) * 17;
        const float* p1 = p0 + 4 * 17;
        unsigned a[2][4];
        #pragma unroll
        for (int mt = 0; mt < 2; mt++) {
            a[mt][0] = fas(p0[rd[mt][0]] * p0[re[mt][0]]);
            a[mt][1] = fas(p0[rd[mt][1]] * p0[re[mt][1]]);
            a[mt][2] = fas(p1[rd[mt][0]] * p1[re[mt][0]]);
            a[mt][3] = fas(p1[rd[mt][1]] * p1[re[mt][1]]);
        }
        unsigned b[3][2];
        #pragma unroll
        for (int nt = 0; nt < 3; nt++) {
            int fc = cb + 8 * nt + g;
            b[nt][0] = sBu[(8 * ks + tg) * NW + fc];
            b[nt][1] = sBu[(8 * ks + tg + 4) * NW + fc];
        }
        #pragma unroll
        for (int mt = 0; mt < 2; mt++)
            #pragma unroll
            for (int nt = 0; nt < 3; nt++)
                mma8(c[mt][nt], a[mt][0], a[mt][1], a[mt][2], a[mt][3],
                     b[nt][0], b[nt][1]);
    }

    #pragma unroll
    for (int mt = 0; mt < 2; mt++)
        #pragma unroll
        for (int nt = 0; nt < 3; nt++) {
            int r0 = rb + 16 * mt + g, col = cb + 8 * nt + 2 * tg;
            *(float2*)&st[r0 * NW + col] =
                make_float2(c[mt][nt][0], c[mt][nt][1]);
            *(float2*)&st[(r0 + 8) * NW + col] =
                make_float2(c[mt][nt][2], c[mt][nt][3]);
        }
}

// ---------------------------------------------------------------------------
// Kernel 2: exclusive prefix scan over chunk axis.
// ---------------------------------------------------------------------------
__global__ void k_scan() {
    const int head = blockIdx.x;
    float* base = g_state + (size_t)head * NC * ST_STRIDE;
    for (int i = blockIdx.y * blockDim.x + threadIdx.x; i < ST_STRIDE;
         i += gridDim.y * blockDim.x) {
        float run = 0.f;
        #pragma unroll
        for (int c = 0; c < NC; c++) {
            float t = base[(size_t)c * ST_STRIDE + i];
            base[(size_t)c * ST_STRIDE + i] = run;
            run += t;
        }
    }
}

// ---------------------------------------------------------------------------
// Kernel 3: output. 512 threads. Mirrored row tiles for balanced intra:
// warp (wm, wn): mt0 rows [16wm, 16wm+16), mt1 rows [240-16wm, 256-16wm).
// Every warp does exactly 34 intra mt-steps.
// ---------------------------------------------------------------------------
__global__ __launch_bounds__(512, 1)
void k_main(const float* __restrict__ qin, const float* __restrict__ kin,
            const float* __restrict__ vin, float* __restrict__ out) {
    const int head = blockIdx.x, ch = blockIdx.y;
    extern __shared__ float sm[];
    float* sq  = sm;                    // [256][17], col16 = 1.0 pad
    float* sk  = sq + CS * 17;          // [256][17]
    float* sB  = sk + CS * 17;          // [256][72] V, later state[160][72]
    float* szs = sB + CS * NW;          // [256]
    int*   spd = (int*)(szs + 256);     // [160]
    int*   spe = spd + NP;
    float* sw  = (float*)(spe + NP);    // [160]
    unsigned* sBu = (unsigned*)sB;

    const float* qg = qin + ((size_t)head * LSEQ + (size_t)ch * CS) * DK;
    const float* kg = kin + ((size_t)head * LSEQ + (size_t)ch * CS) * DK;
    const float* vg = vin + ((size_t)head * LSEQ + (size_t)ch * CS) * DV;
    const float* st = g_state + (size_t)(head * NC + ch) * ST_STRIDE;

    const int tid = threadIdx.x, warp = tid >> 5, lane = tid & 31;
    const int wm = warp >> 1, wn = warp & 1, g = lane >> 2, tg = lane & 3;
    int rbase[2];
    rbase[0] = 16 * wm;
    rbase[1] = 240 - 16 * wm;

    for (int i = tid; i < CS * DK; i += 512) {
        int r = i >> 4, cc = i & 15;
        sq[r * 17 + cc] = f2tf(qg[i] * 0.25f);
        sk[r * 17 + cc] = f2tf(kg[i]);
    }
    if (tid < 256) { sq[tid * 17 + 16] = 1.0f; szs[tid] = 0.f; }
    for (int i = tid; i < CS * 16; i += 512) {
        int cc = i >> 4, f4 = (i & 15) * 4;
        float4 v = *(const float4*)&vg[cc * 64 + f4];
        *(uint4*)&sBu[cc * NW + f4] =
            make_uint4(f2t(v.x), f2t(v.y), f2t(v.z), f2t(v.w));
    }
    lut_build(spd, spe, sw, tid);
    __syncthreads();

    // Q fragments per mirrored tile (K=16 split as 2 x K=8)
    unsigned qf[2][2][4];
    #pragma unroll
    for (int mt = 0; mt < 2; mt++)
        #pragma unroll
        for (int ks = 0; ks < 2; ks++) {
            int r0 = rbase[mt] + g;
            qf[mt][ks][0] = fas(sq[r0 * 17 + 8 * ks + tg]);
            qf[mt][ks][1] = fas(sq[(r0 + 8) * 17 + 8 * ks + tg]);
            qf[mt][ks][2] = fas(sq[r0 * 17 + 8 * ks + tg + 4]);
            qf[mt][ks][3] = fas(sq[(r0 + 8) * 17 + 8 * ks + tg + 4]);
        }

    float c[2][5][4];
    #pragma unroll
    for (int mt = 0; mt < 2; mt++)
        #pragma unroll
        for (int nt = 0; nt < 5; nt++)
            #pragma unroll
            for (int u = 0; u < 4; u++) c[mt][nt][u] = 0.f;

    float zp[2][2];
    zp[0][0] = zp[0][1] = zp[1][0] = zp[1][1] = 0.f;
    const int srcA = (lane & ~3) + (tg >> 1), srcB = srcA + 2;
    const bool od = tg & 1;

    // ---- intra: barrier-free, per-tile column sweep ----
    #pragma unroll
    for (int mt = 0; mt < 2; mt++) {
        const int R = rbase[mt];
        const int nsteps = R / 8 + 2;       // cols [0, R+16)
        const int r0 = R + g;
        for (int js = 0; js < nsteps; js++) {
            int jc = 8 * js + g;
            unsigned b00 = fas(sk[jc * 17 + tg]);
            unsigned b01 = fas(sk[jc * 17 + tg + 4]);
            unsigned b10 = fas(sk[jc * 17 + 8 + tg]);
            unsigned b11 = fas(sk[jc * 17 + 8 + tg + 4]);
            float sf[4] = {0.f, 0.f, 0.f, 0.f};
            mma8(sf, qf[mt][0][0], qf[mt][0][1], qf[mt][0][2],
                 qf[mt][0][3], b00, b01);
            mma8(sf, qf[mt][1][0], qf[mt][1][1], qf[mt][1][2],
                 qf[mt][1][3], b10, b11);
            int jg = 8 * js + 2 * tg;
            float s0 = sf[0], s1 = sf[1], s2 = sf[2], s3 = sf[3];
            float v0 = (r0 >= jg)     ? fmaf(0.5f * s0, s0, s0 + 1.f) : 0.f;
            float v1 = (r0 >= jg + 1) ? fmaf(0.5f * s1, s1, s1 + 1.f) : 0.f;
            float v2 = (r0 + 8 >= jg)     ? fmaf(0.5f * s2, s2, s2 + 1.f) : 0.f;
            float v3 = (r0 + 8 >= jg + 1) ? fmaf(0.5f * s3, s3, s3 + 1.f) : 0.f;
            zp[mt][0] += v0 + v1;
            zp[mt][1] += v2 + v3;
            unsigned u0 = f2t(v0), u1 = f2t(v1);
            unsigned u2 = f2t(v2), u3 = f2t(v3);
            unsigned e0 = shflu(u0, srcA), o0 = shflu(u1, srcA);
            unsigned e1 = shflu(u2, srcA), o1 = shflu(u3, srcA);
            unsigned e2 = shflu(u0, srcB), o2 = shflu(u1, srcB);
            unsigned e3 = shflu(u2, srcB), o3 = shflu(u3, srcB);
            unsigned af0 = od ? o0 : e0;
            unsigned af1 = od ? o1 : e1;
            unsigned af2 = od ? o2 : e2;
            unsigned af3 = od ? o3 : e3;
            #pragma unroll
            for (int nt = 0; nt < 4; nt++) {
                int fc = 32 * wn + 8 * nt + g;
                unsigned bv0 = sBu[(8 * js + tg) * NW + fc];
                unsigned bv1 = sBu[(8 * js + tg + 4) * NW + fc];
                mma8(c[mt][nt], af0, af1, af2, af3, bv0, bv1);
            }
        }
    }

    // intra z merge: wn==0 warps own their rows exclusively
    if (wn == 0) {
        #pragma unroll
        for (int mt = 0; mt < 2; mt++)
            #pragma unroll
            for (int h = 0; h < 2; h++) {
                float v = zp[mt][h];
                v += __shfl_xor_sync(0xffffffffu, v, 1);
                v += __shfl_xor_sync(0xffffffffu, v, 2);
                if (tg == 0) szs[rbase[mt] + g + 8 * h] += v;
            }
    }
    __syncthreads();   // V reads + szs intra writes complete

    // restage sB <- w * scanned state [160][72]
    for (int i = tid; i < NP * 18; i += 512) {
        int pp = i / 18, f4 = (i - pp * 18) * 4;
        float w = sw[pp];
        float4 vv = *(const float4*)&st[pp * NW + f4];
        *(uint4*)&sBu[pp * NW + f4] =
            make_uint4(f2t(w * vv.x), f2t(w * vv.y),
                       f2t(w * vv.z), f2t(w * vv.w));
    }
    __syncthreads();

    // ---- inter: C[256x72] += A[256x160] @ Bstate[160x72], unrolled ----
    const int ntn = 4 + wn, colb = 32 * wn;
    #pragma unroll 5
    for (int ks = 0; ks < 20; ks++) {
        int p0 = 8 * ks + tg, p1 = p0 + 4;
        int d0 = spd[p0], e0 = spe[p0];
        int d1 = spd[p1], e1 = spe[p1];
        unsigned a[2][4];
        #pragma unroll
        for (int mt = 0; mt < 2; mt++) {
            const float* qr0 = sq + (rbase[mt] + g) * 17;
            const float* qr1 = qr0 + 8 * 17;
            a[mt][0] = fas(qr0[d0] * qr0[e0]);
            a[mt][1] = fas(qr1[d0] * qr1[e0]);
            a[mt][2] = fas(qr0[d1] * qr0[e1]);
            a[mt][3] = fas(qr1[d1] * qr1[e1]);
        }
        unsigned b[5][2];
        #pragma unroll
        for (int nt = 0; nt < 5; nt++) {
            if (nt < ntn) {
                int fc = colb + 8 * nt + g;
                b[nt][0] = sBu[(8 * ks + tg) * NW + fc];
                b[nt][1] = sBu[(8 * ks + tg + 4) * NW + fc];
            }
        }
        #pragma unroll
        for (int mt = 0; mt < 2; mt++)
            #pragma unroll
            for (int nt = 0; nt < 5; nt++)
                if (nt < ntn)
                    mma8(c[mt][nt], a[mt][0], a[mt][1], a[mt][2],
                         a[mt][3], b[nt][0], b[nt][1]);
    }

    // z-inter lives in col 64 = (wn==1, nt==4, first col of pair)
    if (wn == 1 && tg == 0) {
        #pragma unroll
        for (int mt = 0; mt < 2; mt++) {
            int r0 = rbase[mt] + g;
            szs[r0]     += c[mt][4][0];
            szs[r0 + 8] += c[mt][4][2];
        }
    }
    __syncthreads();

    // ---- epilogue: divide by z, store ----
    float* og = out + ((size_t)head * LSEQ + (size_t)ch * CS) * DV;
    #pragma unroll
    for (int mt = 0; mt < 2; mt++) {
        int r0 = rbase[mt] + g;
        float z0 = 1.f / (szs[r0] + 1e-6f);
        float z1 = 1.f / (szs[r0 + 8] + 1e-6f);
        #pragma unroll
        for (int nt = 0; nt < 4; nt++) {
            int f = 32 * wn + 8 * nt + 2 * tg;
            *(float2*)&og[r0 * 64 + f] =
                make_float2(c[mt][nt][0] * z0, c[mt][nt][1] * z0);
            *(float2*)&og[(r0 + 8) * 64 + f] =
                make_float2(c[mt][nt][2] * z1, c[mt][nt][3] * z1);
        }
    }
}

// ---------------------------------------------------------------------------
extern "C" void kernel_launch(void* const* d_in, const int* in_sizes, int n_in,
                              void* d_out, int out_size) {
    const float* q = (const float*)d_in[0];
    const float* k = (const float*)d_in[1];
    const float* v = (const float*)d_in[2];
    float* out = (float*)d_out;

    const int smem1 = (CS * 17 + CS * NW + 3 * NP) * (int)sizeof(float);
    const int smem3 = (CS * 17 * 2 + CS * NW + 256 + 3 * NP) * (int)sizeof(float);

    cudaFuncSetAttribute(k_build, cudaFuncAttributeMaxDynamicSharedMemorySize, smem1);
    cudaFuncSetAttribute(k_main,  cudaFuncAttributeMaxDynamicSharedMemorySize, smem3);

    k_build<<<dim3(BH, NC), 480, smem1>>>(k, v);
    k_scan<<<dim3(BH, 16), 256>>>();
    k_main<<<dim3(BH, NC), 512, smem3>>>(q, k, v, out);
}

// round 9
// speedup vs baseline: 2.1071x; 1.1090x over previous
#include <cuda_runtime.h>
#include <cstdint>

#define BH   32
#define LSEQ 4096
#define DK   16
#define DV   64
#define CS   256
#define NC   16

// Symmetric-pair state: 136 pair rows (d<=e) + 16 linear rows + 1 ones row,
// padded to 160 rows x 72 cols (64 v-cols + 1 aux-sum col + 7 zero pads).
#define NP   160
#define NW   72
#define ST_STRIDE (NP * NW)   // 11520

__device__ float g_state[(size_t)BH * NC * ST_STRIDE];

__device__ __forceinline__ unsigned f2t(float x) {
    unsigned u;
    asm("cvt.rna.tf32.f32 %0, %1;" : "=r"(u) : "f"(x));
    return u;
}
__device__ __forceinline__ float f2tf(float x) { return __uint_as_float(f2t(x)); }
__device__ __forceinline__ unsigned fas(float x) { return __float_as_uint(x); }
__device__ __forceinline__ unsigned shflu(unsigned v, int src) {
    return __shfl_sync(0xffffffffu, v, src);
}

__device__ __forceinline__ void mma8(float* c, unsigned a0, unsigned a1,
                                     unsigned a2, unsigned a3,
                                     unsigned b0, unsigned b1) {
    asm volatile(
        "mma.sync.aligned.m16n8k8.row.col.f32.tf32.tf32.f32 "
        "{%0,%1,%2,%3},{%4,%5,%6,%7},{%8,%9},{%0,%1,%2,%3};"
        : "+f"(c[0]), "+f"(c[1]), "+f"(c[2]), "+f"(c[3])
        : "r"(a0), "r"(a1), "r"(a2), "r"(a3), "r"(b0), "r"(b1));
}

// p -> (d, e, w).  d,e in [0,16]; index 16 hits the pad column (=1.0f).
__device__ __forceinline__ void lut_build(int* spd, int* spe, float* sw, int tid) {
    if (tid < NP) {
        int p = tid, d = 0, e;
        float w;
        if (p < 136) {
            int base = 0;
            while (base + (16 - d) <= p) { base += 16 - d; d++; }
            e = d + (p - base);
            w = (d == e) ? 0.5f : 1.0f;
        } else if (p < 152) { d = p - 136; e = 16; w = 1.f; }
        else if (p == 152) { d = 16; e = 16; w = 1.f; }
        else               { d = 16; e = 16; w = 0.f; }
        spd[p] = d; spe[p] = e; sw[p] = w;
    }
}

// ---------------------------------------------------------------------------
// Kernel 1: state build = single GEMM  st[160x72] = A[160x256] @ B[256x72]
// Full B staged once; ONE barrier; unrolled 32-step mma stream.
// 480 threads = 15 warps, 2 CTAs/SM (regs capped).
// ---------------------------------------------------------------------------
__global__ __launch_bounds__(480, 2)
void k_build(const float* __restrict__ kin, const float* __restrict__ vin) {
    const int head = blockIdx.x, ch = blockIdx.y;
    extern __shared__ float sm[];
    float* sk = sm;                     // [256][17], col 16 = 1.0 pad
    float* sB = sk + CS * 17;           // [256][72] full V + aux
    int*   spd = (int*)(sB + CS * NW);  // [160]
    int*   spe = spd + NP;              // [160]
    float* sw  = (float*)(spe + NP);    // [160]
    unsigned* sBu = (unsigned*)sB;

    const float* kg = kin + ((size_t)head * LSEQ + (size_t)ch * CS) * DK;
    const float* vg = vin + ((size_t)head * LSEQ + (size_t)ch * CS) * DV;
    float* st = g_state + (size_t)(head * NC + ch) * ST_STRIDE;

    const int tid = threadIdx.x, warp = tid >> 5, lane = tid & 31;
    const int wm = warp / 3, wn = warp % 3, g = lane >> 2, tg = lane & 3;
    const int rb = 32 * wm, cb = 24 * wn;

    for (int i = tid; i < CS * DK; i += 480)
        sk[(i >> 4) * 17 + (i & 15)] = f2tf(kg[i]);
    for (int i = tid; i < CS; i += 480) sk[i * 17 + 16] = 1.0f;
    for (int i = tid; i < CS * 18; i += 480) {
        int cc = i / 18, f4 = (i - cc * 18) * 4;
        uint4 w;
        if (f4 < 64) {
            float4 vv = *(const float4*)&vg[cc * 64 + f4];
            w = make_uint4(f2t(vv.x), f2t(vv.y), f2t(vv.z), f2t(vv.w));
        } else {
            w = make_uint4(f4 == 64 ? 0x3f800000u : 0u, 0u, 0u, 0u);
        }
        *(uint4*)&sBu[cc * NW + f4] = w;
    }
    lut_build(spd, spe, sw, tid);
    __syncthreads();

    int rd[2][2], re[2][2];
    #pragma unroll
    for (int mt = 0; mt < 2; mt++) {
        int r0 = rb + 16 * mt + g;
        rd[mt][0] = spd[r0];     re[mt][0] = spe[r0];
        rd[mt][1] = spd[r0 + 8]; re[mt][1] = spe[r0 + 8];
    }

    float c[2][3][4];
    #pragma unroll
    for (int mt = 0; mt < 2; mt++)
        #pragma unroll
        for (int nt = 0; nt < 3; nt++)
            #pragma unroll
            for (int u = 0; u < 4; u++) c[mt][nt][u] = 0.f;

    #pragma unroll 4
    for (int ks = 0; ks < 32; ks++) {
        const float* p0 = sk + (8 * ks + tg) * 17;
        const float* p1 = p0 + 4 * 17;
        unsigned a[2][4];
        #pragma unroll
        for (int mt = 0; mt < 2; mt++) {
            a[mt][0] = fas(p0[rd[mt][0]] * p0[re[mt][0]]);
            a[mt][1] = fas(p0[rd[mt][1]] * p0[re[mt][1]]);
            a[mt][2] = fas(p1[rd[mt][0]] * p1[re[mt][0]]);
            a[mt][3] = fas(p1[rd[mt][1]] * p1[re[mt][1]]);
        }
        unsigned b[3][2];
        #pragma unroll
        for (int nt = 0; nt < 3; nt++) {
            int fc = cb + 8 * nt + g;
            b[nt][0] = sBu[(8 * ks + tg) * NW + fc];
            b[nt][1] = sBu[(8 * ks + tg + 4) * NW + fc];
        }
        #pragma unroll
        for (int mt = 0; mt < 2; mt++)
            #pragma unroll
            for (int nt = 0; nt < 3; nt++)
                mma8(c[mt][nt], a[mt][0], a[mt][1], a[mt][2], a[mt][3],
                     b[nt][0], b[nt][1]);
    }

    #pragma unroll
    for (int mt = 0; mt < 2; mt++)
        #pragma unroll
        for (int nt = 0; nt < 3; nt++) {
            int r0 = rb + 16 * mt + g, col = cb + 8 * nt + 2 * tg;
            *(float2*)&st[r0 * NW + col] =
                make_float2(c[mt][nt][0], c[mt][nt][1]);
            *(float2*)&st[(r0 + 8) * NW + col] =
                make_float2(c[mt][nt][2], c[mt][nt][3]);
        }
}

// ---------------------------------------------------------------------------
// Kernel 2: exclusive prefix scan over chunk axis.
// ---------------------------------------------------------------------------
__global__ void k_scan() {
    const int head = blockIdx.x;
    float* base = g_state + (size_t)head * NC * ST_STRIDE;
    for (int i = blockIdx.y * blockDim.x + threadIdx.x; i < ST_STRIDE;
         i += gridDim.y * blockDim.x) {
        float run = 0.f;
        #pragma unroll
        for (int c = 0; c < NC; c++) {
            float t = base[(size_t)c * ST_STRIDE + i];
            base[(size_t)c * ST_STRIDE + i] = run;
            run += t;
        }
    }
}

// ---------------------------------------------------------------------------
// Kernel 3: output. 512 threads, 2 CTAs/SM. Mirrored row tiles (34 steps per
// warp). Inter-z computed scalar (no 5th accumulator tile, no divergence).
// ---------------------------------------------------------------------------
__global__ __launch_bounds__(512, 2)
void k_main(const float* __restrict__ qin, const float* __restrict__ kin,
            const float* __restrict__ vin, float* __restrict__ out) {
    const int head = blockIdx.x, ch = blockIdx.y;
    extern __shared__ float sm[];
    float* sq  = sm;                    // [256][17], col16 = 1.0 pad
    float* sk  = sq + CS * 17;          // [256][17]
    float* sB  = sk + CS * 17;          // [256][72] V, later state[160][72]
    float* szs = sB + CS * NW;          // [256]
    int*   spd = (int*)(szs + 256);     // [160]
    int*   spe = spd + NP;
    float* sw  = (float*)(spe + NP);    // [160]
    float* swst = sw + NP;              // [160] w*state[:,64]
    unsigned* sBu = (unsigned*)sB;

    const float* qg = qin + ((size_t)head * LSEQ + (size_t)ch * CS) * DK;
    const float* kg = kin + ((size_t)head * LSEQ + (size_t)ch * CS) * DK;
    const float* vg = vin + ((size_t)head * LSEQ + (size_t)ch * CS) * DV;
    const float* st = g_state + (size_t)(head * NC + ch) * ST_STRIDE;

    const int tid = threadIdx.x, warp = tid >> 5, lane = tid & 31;
    const int wm = warp >> 1, wn = warp & 1, g = lane >> 2, tg = lane & 3;
    int rbase[2];
    rbase[0] = 16 * wm;
    rbase[1] = 240 - 16 * wm;

    for (int i = tid; i < CS * DK; i += 512) {
        int r = i >> 4, cc = i & 15;
        sq[r * 17 + cc] = f2tf(qg[i] * 0.25f);
        sk[r * 17 + cc] = f2tf(kg[i]);
    }
    if (tid < 256) { sq[tid * 17 + 16] = 1.0f; szs[tid] = 0.f; }
    for (int i = tid; i < CS * 16; i += 512) {
        int cc = i >> 4, f4 = (i & 15) * 4;
        float4 v = *(const float4*)&vg[cc * 64 + f4];
        *(uint4*)&sBu[cc * NW + f4] =
            make_uint4(f2t(v.x), f2t(v.y), f2t(v.z), f2t(v.w));
    }
    lut_build(spd, spe, sw, tid);
    __syncthreads();

    // Q fragments per mirrored tile (K=16 split as 2 x K=8)
    unsigned qf[2][2][4];
    #pragma unroll
    for (int mt = 0; mt < 2; mt++)
        #pragma unroll
        for (int ks = 0; ks < 2; ks++) {
            int r0 = rbase[mt] + g;
            qf[mt][ks][0] = fas(sq[r0 * 17 + 8 * ks + tg]);
            qf[mt][ks][1] = fas(sq[(r0 + 8) * 17 + 8 * ks + tg]);
            qf[mt][ks][2] = fas(sq[r0 * 17 + 8 * ks + tg + 4]);
            qf[mt][ks][3] = fas(sq[(r0 + 8) * 17 + 8 * ks + tg + 4]);
        }

    float c[2][4][4];
    #pragma unroll
    for (int mt = 0; mt < 2; mt++)
        #pragma unroll
        for (int nt = 0; nt < 4; nt++)
            #pragma unroll
            for (int u = 0; u < 4; u++) c[mt][nt][u] = 0.f;

    float zp[2][2];
    zp[0][0] = zp[0][1] = zp[1][0] = zp[1][1] = 0.f;
    const int srcA = (lane & ~3) + (tg >> 1), srcB = srcA + 2;
    const bool od = tg & 1;

    // ---- intra: barrier-free, per-tile column sweep ----
    #pragma unroll
    for (int mt = 0; mt < 2; mt++) {
        const int R = rbase[mt];
        const int nsteps = R / 8 + 2;       // cols [0, R+16)
        const int r0 = R + g;
        for (int js = 0; js < nsteps; js++) {
            int jc = 8 * js + g;
            unsigned b00 = fas(sk[jc * 17 + tg]);
            unsigned b01 = fas(sk[jc * 17 + tg + 4]);
            unsigned b10 = fas(sk[jc * 17 + 8 + tg]);
            unsigned b11 = fas(sk[jc * 17 + 8 + tg + 4]);
            float sf[4] = {0.f, 0.f, 0.f, 0.f};
            mma8(sf, qf[mt][0][0], qf[mt][0][1], qf[mt][0][2],
                 qf[mt][0][3], b00, b01);
            mma8(sf, qf[mt][1][0], qf[mt][1][1], qf[mt][1][2],
                 qf[mt][1][3], b10, b11);
            int jg = 8 * js + 2 * tg;
            float s0 = sf[0], s1 = sf[1], s2 = sf[2], s3 = sf[3];
            float v0 = (r0 >= jg)     ? fmaf(0.5f * s0, s0, s0 + 1.f) : 0.f;
            float v1 = (r0 >= jg + 1) ? fmaf(0.5f * s1, s1, s1 + 1.f) : 0.f;
            float v2 = (r0 + 8 >= jg)     ? fmaf(0.5f * s2, s2, s2 + 1.f) : 0.f;
            float v3 = (r0 + 8 >= jg + 1) ? fmaf(0.5f * s3, s3, s3 + 1.f) : 0.f;
            zp[mt][0] += v0 + v1;
            zp[mt][1] += v2 + v3;
            unsigned u0 = f2t(v0), u1 = f2t(v1);
            unsigned u2 = f2t(v2), u3 = f2t(v3);
            unsigned e0 = shflu(u0, srcA), o0 = shflu(u1, srcA);
            unsigned e1 = shflu(u2, srcA), o1 = shflu(u3, srcA);
            unsigned e2 = shflu(u0, srcB), o2 = shflu(u1, srcB);
            unsigned e3 = shflu(u2, srcB), o3 = shflu(u3, srcB);
            unsigned af0 = od ? o0 : e0;
            unsigned af1 = od ? o1 : e1;
            unsigned af2 = od ? o2 : e2;
            unsigned af3 = od ? o3 : e3;
            #pragma unroll
            for (int nt = 0; nt < 4; nt++) {
                int fc = 32 * wn + 8 * nt + g;
                unsigned bv0 = sBu[(8 * js + tg) * NW + fc];
                unsigned bv1 = sBu[(8 * js + tg + 4) * NW + fc];
                mma8(c[mt][nt], af0, af1, af2, af3, bv0, bv1);
            }
        }
    }

    // intra z merge: wn==0 warps own their rows exclusively
    if (wn == 0) {
        #pragma unroll
        for (int mt = 0; mt < 2; mt++)
            #pragma unroll
            for (int h = 0; h < 2; h++) {
                float v = zp[mt][h];
                v += __shfl_xor_sync(0xffffffffu, v, 1);
                v += __shfl_xor_sync(0xffffffffu, v, 2);
                if (tg == 0) szs[rbase[mt] + g + 8 * h] += v;
            }
    }
    __syncthreads();   // V reads + szs intra writes complete

    // restage sB <- w * scanned state [160][72]; swst <- w * state[:,64]
    for (int i = tid; i < NP * 16; i += 512) {
        int pp = i >> 4, f4 = (i & 15) * 4;
        float w = sw[pp];
        float4 vv = *(const float4*)&st[pp * NW + f4];
        *(uint4*)&sBu[pp * NW + f4] =
            make_uint4(f2t(w * vv.x), f2t(w * vv.y),
                       f2t(w * vv.z), f2t(w * vv.w));
    }
    if (tid < NP) swst[tid] = sw[tid] * st[tid * NW + 64];
    __syncthreads();

    // inter z (scalar): z_inter[row] = sum_p q_d q_e * (w*state[p][64])
    if (tid < 256) {
        const float* qr = sq + tid * 17;
        float zi = 0.f;
        #pragma unroll 8
        for (int p = 0; p < 153; p++)
            zi = fmaf(qr[spd[p]] * qr[spe[p]], swst[p], zi);
        szs[tid] += zi;
    }

    // ---- inter: C[256x64] += A[256x160] @ Bstate[160x64], unrolled ----
    const int colb = 32 * wn;
    #pragma unroll 5
    for (int ks = 0; ks < 20; ks++) {
        int p0 = 8 * ks + tg, p1 = p0 + 4;
        int d0 = spd[p0], e0 = spe[p0];
        int d1 = spd[p1], e1 = spe[p1];
        unsigned a[2][4];
        #pragma unroll
        for (int mt = 0; mt < 2; mt++) {
            const float* qr0 = sq + (rbase[mt] + g) * 17;
            const float* qr1 = qr0 + 8 * 17;
            a[mt][0] = fas(qr0[d0] * qr0[e0]);
            a[mt][1] = fas(qr1[d0] * qr1[e0]);
            a[mt][2] = fas(qr0[d1] * qr0[e1]);
            a[mt][3] = fas(qr1[d1] * qr1[e1]);
        }
        unsigned b[4][2];
        #pragma unroll
        for (int nt = 0; nt < 4; nt++) {
            int fc = colb + 8 * nt + g;
            b[nt][0] = sBu[(8 * ks + tg) * NW + fc];
            b[nt][1] = sBu[(8 * ks + tg + 4) * NW + fc];
        }
        #pragma unroll
        for (int mt = 0; mt < 2; mt++)
            #pragma unroll
            for (int nt = 0; nt < 4; nt++)
                mma8(c[mt][nt], a[mt][0], a[mt][1], a[mt][2],
                     a[mt][3], b[nt][0], b[nt][1]);
    }
    __syncthreads();

    // ---- epilogue: divide by z, store ----
    float* og = out + ((size_t)head * LSEQ + (size_t)ch * CS) * DV;
    #pragma unroll
    for (int mt = 0; mt < 2; mt++) {
        int r0 = rbase[mt] + g;
        float z0 = 1.f / (szs[r0] + 1e-6f);
        float z1 = 1.f / (szs[r0 + 8] + 1e-6f);
        #pragma unroll
        for (int nt = 0; nt < 4; nt++) {
            int f = 32 * wn + 8 * nt + 2 * tg;
            *(float2*)&og[r0 * 64 + f] =
                make_float2(c[mt][nt][0] * z0, c[mt][nt][1] * z0);
            *(float2*)&og[(r0 + 8) * 64 + f] =
                make_float2(c[mt][nt][2] * z1, c[mt][nt][3] * z1);
        }
    }
}

// ---------------------------------------------------------------------------
extern "C" void kernel_launch(void* const* d_in, const int* in_sizes, int n_in,
                              void* d_out, int out_size) {
    const float* q = (const float*)d_in[0];
    const float* k = (const float*)d_in[1];
    const float* v = (const float*)d_in[2];
    float* out = (float*)d_out;

    const int smem1 = (CS * 17 + CS * NW + 3 * NP) * (int)sizeof(float);
    const int smem3 = (CS * 17 * 2 + CS * NW + 256 + 4 * NP) * (int)sizeof(float);

    cudaFuncSetAttribute(k_build, cudaFuncAttributeMaxDynamicSharedMemorySize, smem1);
    cudaFuncSetAttribute(k_main,  cudaFuncAttributeMaxDynamicSharedMemorySize, smem3);

    k_build<<<dim3(BH, NC), 480, smem1>>>(k, v);
    k_scan<<<dim3(BH, 16), 256>>>();
    k_main<<<dim3(BH, NC), 512, smem3>>>(q, k, v, out);
}